// round 4
// baseline (speedup 1.0000x reference)
#include <cuda_runtime.h>

// DifferentiableNERF, round 4.
// One block (128 threads, 4 warps) per chain; thread owns SEG=4 steps.
// Pass 1: simulate 4 steps from canonical init triplet into REGISTERS,
//         then 9x STS.128 into a linear SMEM buffer laid out in OUTPUT order
//         (lin[s] corresponds to out[s+9]).
// Conjugated-space scan (matrix form): H' = F(end) o F0^-1; warp Kogge-Stone
//         + 4-way cross-warp combine => exclusive prefix = W directly.
// Pass 2: 3 rounds of (3x LDS.128 -> transform 4 points by W -> 3x STS.128),
//         in place in the linear buffer.
// Writeout: pure coalesced float4 copy (no index arithmetic beyond +128).

namespace {

constexpr int L_CONST = 512;
constexpr int NSTEP = L_CONST - 1;   // 511
constexpr int SEG = 4;               // steps per thread
constexpr int THREADS = 128;         // 4 warps = 1 chain
constexpr int CHAIN_FLOATS = 3 * L_CONST * 3;   // 4608
constexpr int LIN_WORDS = 4640;      // 511*9 = 4599 valid, padded

struct V3 { float x, y, z; };

__device__ __forceinline__ V3 vsub(V3 a, V3 b) { return {a.x - b.x, a.y - b.y, a.z - b.z}; }
__device__ __forceinline__ V3 vcross(V3 a, V3 b) {
    return { a.y * b.z - a.z * b.y,
             a.z * b.x - a.x * b.z,
             a.x * b.y - a.y * b.x };
}
__device__ __forceinline__ float vdot(V3 a, V3 b) { return a.x * b.x + a.y * b.y + a.z * b.z; }
__device__ __forceinline__ V3 vunit(V3 a) {
    float r = rsqrtf(fmaxf(vdot(a, a), 1e-30f));
    return { a.x * r, a.y * r, a.z * r };
}

struct Aff { float m[9]; float t[3]; };

__device__ __forceinline__ Aff identityAff() {
    Aff r;
    r.m[0] = 1.f; r.m[1] = 0.f; r.m[2] = 0.f;
    r.m[3] = 0.f; r.m[4] = 1.f; r.m[5] = 0.f;
    r.m[6] = 0.f; r.m[7] = 0.f; r.m[8] = 1.f;
    r.t[0] = 0.f; r.t[1] = 0.f; r.t[2] = 0.f;
    return r;
}

// (A o B)(x) = A(B(x))
__device__ __forceinline__ Aff compose(const Aff& A, const Aff& B) {
    Aff r;
#pragma unroll
    for (int i = 0; i < 3; i++) {
#pragma unroll
        for (int j = 0; j < 3; j++) {
            r.m[3 * i + j] = A.m[3 * i + 0] * B.m[0 + j]
                           + A.m[3 * i + 1] * B.m[3 + j]
                           + A.m[3 * i + 2] * B.m[6 + j];
        }
        r.t[i] = A.m[3 * i + 0] * B.t[0]
               + A.m[3 * i + 1] * B.t[1]
               + A.m[3 * i + 2] * B.t[2] + A.t[i];
    }
    return r;
}

// ex = unit(c-b), ez = unit(cross(b-a, ex)), ey = ez x ex, origin = c.
__device__ __forceinline__ Aff frameOf(V3 a, V3 b, V3 c) {
    V3 ex = vunit(vsub(c, b));
    V3 ez = vunit(vcross(vsub(b, a), ex));
    V3 ey = vcross(ez, ex);
    Aff F;
    F.m[0] = ex.x; F.m[1] = ey.x; F.m[2] = ez.x;
    F.m[3] = ex.y; F.m[4] = ey.y; F.m[5] = ez.y;
    F.m[6] = ex.z; F.m[7] = ey.z; F.m[8] = ez.z;
    F.t[0] = c.x;  F.t[1] = c.y;  F.t[2] = c.z;
    return F;
}

__device__ __forceinline__ Aff invRigid(const Aff& A) {
    Aff r;
    r.m[0] = A.m[0]; r.m[1] = A.m[3]; r.m[2] = A.m[6];
    r.m[3] = A.m[1]; r.m[4] = A.m[4]; r.m[5] = A.m[7];
    r.m[6] = A.m[2]; r.m[7] = A.m[5]; r.m[8] = A.m[8];
#pragma unroll
    for (int i = 0; i < 3; i++) {
        r.t[i] = -(r.m[3 * i + 0] * A.t[0] + r.m[3 * i + 1] * A.t[1] + r.m[3 * i + 2] * A.t[2]);
    }
    return r;
}

__device__ __forceinline__ V3 place(V3 a, V3 b, V3 c, float ang, float len, float tor) {
    V3 bc = vunit(vsub(c, b));
    V3 n  = vunit(vcross(vsub(b, a), bc));
    V3 nbc = vcross(n, bc);
    float st, ct;
    __sincosf(tor, &st, &ct);
    float sa, ca;
    __sincosf(ang, &sa, &ca);
    float d0 = -len * ca;
    float d1 = len * ct * sa;
    float d2 = len * st * sa;
    return { c.x + bc.x * d0 + nbc.x * d1 + n.x * d2,
             c.y + bc.y * d0 + nbc.y * d1 + n.y * d2,
             c.z + bc.z * d0 + nbc.z * d1 + n.z * d2 };
}

__device__ __forceinline__ void stepFn(V3& a, V3& b, V3& c,
                                       float psi_i, float omega_i, float phi_i,
                                       float len_cn, float len_nca, float len_cac,
                                       float ang_cacn, float ang_cnca, float ang_ncac) {
    V3 n  = place(a, b, c, ang_cacn, len_cn, psi_i);
    V3 ca = place(b, c, n, ang_cnca, len_nca, omega_i);
    V3 cc = place(c, n, ca, ang_ncac, len_cac, phi_i);
    a = n; b = ca; c = cc;
}

__device__ __forceinline__ Aff shflUpAff(const Aff& A, int delta) {
    Aff r;
#pragma unroll
    for (int k = 0; k < 9; k++) r.m[k] = __shfl_up_sync(0xffffffffu, A.m[k], delta);
#pragma unroll
    for (int k = 0; k < 3; k++) r.t[k] = __shfl_up_sync(0xffffffffu, A.t[k], delta);
    return r;
}

__constant__ float c9[9] = {
    17.047f, 14.099f, 3.625f,
    16.967f, 12.784f, 4.338f,
    15.685f, 12.755f, 5.133f
};

__global__ __launch_bounds__(THREADS, 6)
void nerf_kernel(const float* __restrict__ phi,
                 const float* __restrict__ psi,
                 const float* __restrict__ omega,
                 const float* __restrict__ bl,
                 const float* __restrict__ ba,
                 float* __restrict__ out) {
    __shared__ __align__(16) float lin[LIN_WORDS];   // output-ordered local/world coords
    __shared__ float warpTot[3][12];                 // inclusive totals of warps 0..2

    const int tid  = threadIdx.x;
    const int lane = tid & 31;
    const int warp = tid >> 5;
    const int chain = blockIdx.x;

    const int base = tid * SEG;

    const V3 A0 = {17.047f, 14.099f, 3.625f};
    const V3 B0 = {16.967f, 12.784f, 4.338f};
    const V3 C0 = {15.685f, 12.755f, 5.133f};

    const float* __restrict__ phiR = phi   + (size_t)chain * L_CONST;
    const float* __restrict__ psiS = psi   + (size_t)chain * L_CONST + base;
    const float* __restrict__ omgS = omega + (size_t)chain * L_CONST + base;
    const float* __restrict__ blS  = bl + (size_t)chain * L_CONST * 3 + 3 * base;
    const float* __restrict__ baS  = ba + (size_t)chain * L_CONST * 3 + 3 * base;

    // ---- Batched vector loads of this thread's 4-step inputs ----
    float4 psq = *(const float4*)psiS;
    float4 omq = *(const float4*)omgS;
    float4 blq[3], baq[3];
#pragma unroll
    for (int q = 0; q < 3; q++) {
        blq[q] = *(const float4*)(blS + 4 * q);
        baq[q] = *(const float4*)(baS + 4 * q);
    }
    float4 phq = *(const float4*)(phiR + base);   // phi[base .. base+3]
    float ph3 = __shfl_down_sync(0xffffffffu, phq.x, 1);   // phi[base+4]
    if (lane == 31) {
        int ip = base + SEG;
        ph3 = (ip < L_CONST) ? phiR[ip] : 0.f;
    }
    float phv[4] = { phq.y, phq.z, phq.w, ph3 };
    const float* psf = (const float*)&psq;
    const float* omf = (const float*)&omq;
    const float* blf = (const float*)blq;
    const float* baf = (const float*)baq;

    // ---- Pass 1: simulate segment from canonical init into registers ----
    float tr[SEG * 9];
    V3 a = A0, b = B0, c = C0;
#pragma unroll
    for (int t = 0; t < SEG; t++) {
        int i = base + t;
        if (i < NSTEP) {
            stepFn(a, b, c,
                   psf[t], omf[t], phv[t],
                   blf[3 * t + 2], blf[3 * t + 0], blf[3 * t + 1],
                   baf[3 * t + 1], baf[3 * t + 2], baf[3 * t + 0]);
        }
        tr[9 * t + 0] = a.x; tr[9 * t + 1] = a.y; tr[9 * t + 2] = a.z;
        tr[9 * t + 3] = b.x; tr[9 * t + 4] = b.y; tr[9 * t + 5] = b.z;
        tr[9 * t + 6] = c.x; tr[9 * t + 7] = c.y; tr[9 * t + 8] = c.z;
    }

    // Spill local trajectory to linear SMEM (output order): 9x STS.128
    {
        float4* linv = (float4*)lin;
        const float4* trv = (const float4*)tr;
#pragma unroll
        for (int j = 0; j < 9; j++) linv[9 * tid + j] = trv[j];
    }

    // ---- Conjugated segment transform: H' = F(end) o F0^-1 ----
    const Aff F0i = invRigid(frameOf(A0, B0, C0));
    Aff P = compose(frameOf(a, b, c), F0i);

    // Warp inclusive Kogge-Stone scan
#pragma unroll
    for (int off = 1; off < 32; off <<= 1) {
        Aff prev = shflUpAff(P, off);
        Aff comb = compose(prev, P);
        if (lane >= off) P = comb;
    }

    // Publish warp totals
    if (lane == 31 && warp < 3) {
#pragma unroll
        for (int k = 0; k < 9; k++) warpTot[warp][k] = P.m[k];
#pragma unroll
        for (int k = 0; k < 3; k++) warpTot[warp][9 + k] = P.t[k];
    }

    Aff Pex = shflUpAff(P, 1);   // warp-local exclusive prefix
    __syncthreads();

    // W = warpTot[0] o ... o warpTot[warp-1] o Pex   (exclusive prefix = W)
    Aff W = (lane == 0) ? identityAff() : Pex;
    for (int v = warp - 1; v >= 0; v--) {
        Aff T;
#pragma unroll
        for (int k = 0; k < 9; k++) T.m[k] = warpTot[v][k];
#pragma unroll
        for (int k = 0; k < 3; k++) T.t[k] = warpTot[v][9 + k];
        W = compose(T, W);
    }

    // ---- Pass 2: transform local trajectory in place (vectorized) ----
    {
        float4* linv = (float4*)lin;
#pragma unroll
        for (int r = 0; r < 3; r++) {
            float4 q0 = linv[9 * tid + 3 * r + 0];
            float4 q1 = linv[9 * tid + 3 * r + 1];
            float4 q2 = linv[9 * tid + 3 * r + 2];
            float f[12] = { q0.x, q0.y, q0.z, q0.w,
                            q1.x, q1.y, q1.z, q1.w,
                            q2.x, q2.y, q2.z, q2.w };
#pragma unroll
            for (int p = 0; p < 4; p++) {
                float x = f[3 * p], y = f[3 * p + 1], z = f[3 * p + 2];
                f[3 * p]     = W.m[0] * x + W.m[1] * y + W.m[2] * z + W.t[0];
                f[3 * p + 1] = W.m[3] * x + W.m[4] * y + W.m[5] * z + W.t[1];
                f[3 * p + 2] = W.m[6] * x + W.m[7] * y + W.m[8] * z + W.t[2];
            }
            linv[9 * tid + 3 * r + 0] = make_float4(f[0], f[1], f[2],  f[3]);
            linv[9 * tid + 3 * r + 1] = make_float4(f[4], f[5], f[6],  f[7]);
            linv[9 * tid + 3 * r + 2] = make_float4(f[8], f[9], f[10], f[11]);
        }
    }
    __syncthreads();

    // ---- Writeout: coalesced float4 copy, out[f] = lin[f-9] (f>=9) ----
    float* __restrict__ outC = out + (size_t)chain * CHAIN_FLOATS;
    float4* __restrict__ outV = (float4*)outC;

    // Iteration 0: threads 0..2 cover the init-triplet constants region.
    {
        int q = tid;
        if (q < 3) {
#pragma unroll
            for (int w = 0; w < 4; w++) {
                int f = 4 * q + w;
                outC[f] = (f < 9) ? c9[f] : lin[f - 9];
            }
        } else {
            int s = 4 * q - 9;
            outV[q] = make_float4(lin[s], lin[s + 1], lin[s + 2], lin[s + 3]);
        }
    }
#pragma unroll
    for (int it = 1; it < 9; it++) {
        int q = it * THREADS + tid;
        int s = 4 * q - 9;
        outV[q] = make_float4(lin[s], lin[s + 1], lin[s + 2], lin[s + 3]);
    }
}

} // anonymous namespace

extern "C" void kernel_launch(void* const* d_in, const int* in_sizes, int n_in,
                              void* d_out, int out_size) {
    const float* phi   = (const float*)d_in[0];
    const float* psi   = (const float*)d_in[1];
    const float* omega = (const float*)d_in[2];
    const float* bl    = (const float*)d_in[3];
    const float* ba    = (const float*)d_in[4];

    const int B = in_sizes[0] / L_CONST;

    nerf_kernel<<<B, THREADS>>>(phi, psi, omega, bl, ba, (float*)d_out);
}

// round 5
// speedup vs baseline: 1.4627x; 1.4627x over previous
#include <cuda_runtime.h>

// DifferentiableNERF, round 5.
// R3 structure (conflict-free transposed SMEM, block=128 per chain, SEG=4,
// matrix Kogge-Stone scan) + closed-form frame propagation in pass 1:
// track the orthonormal placement frame (ex,ey,ez,origin); each atom placement
// is sincos + ~26 FMA, with NO normalization (rsqrt) and NO frame re-derivation.
// Segment endpoint frame for the scan is the tracked frame itself.

namespace {

constexpr int L_CONST = 512;
constexpr int NSTEP = L_CONST - 1;   // 511
constexpr int SEG = 4;               // steps per thread
constexpr int THREADS = 128;         // 4 warps = 1 chain
constexpr int CHAIN_FLOATS = 3 * L_CONST * 3;  // 4608
constexpr int ROWS = SEG * 9;        // 36

struct V3 { float x, y, z; };

__device__ __forceinline__ V3 vsub(V3 a, V3 b) { return {a.x - b.x, a.y - b.y, a.z - b.z}; }
__device__ __forceinline__ V3 vcross(V3 a, V3 b) {
    return { a.y * b.z - a.z * b.y,
             a.z * b.x - a.x * b.z,
             a.x * b.y - a.y * b.x };
}
__device__ __forceinline__ float vdot(V3 a, V3 b) { return a.x * b.x + a.y * b.y + a.z * b.z; }
__device__ __forceinline__ V3 vunit(V3 a) {
    float r = rsqrtf(fmaxf(vdot(a, a), 1e-30f));
    return { a.x * r, a.y * r, a.z * r };
}

struct Aff { float m[9]; float t[3]; };

__device__ __forceinline__ Aff identityAff() {
    Aff r;
    r.m[0] = 1.f; r.m[1] = 0.f; r.m[2] = 0.f;
    r.m[3] = 0.f; r.m[4] = 1.f; r.m[5] = 0.f;
    r.m[6] = 0.f; r.m[7] = 0.f; r.m[8] = 1.f;
    r.t[0] = 0.f; r.t[1] = 0.f; r.t[2] = 0.f;
    return r;
}

// (A o B)(x) = A(B(x))
__device__ __forceinline__ Aff compose(const Aff& A, const Aff& B) {
    Aff r;
#pragma unroll
    for (int i = 0; i < 3; i++) {
#pragma unroll
        for (int j = 0; j < 3; j++) {
            r.m[3 * i + j] = A.m[3 * i + 0] * B.m[0 + j]
                           + A.m[3 * i + 1] * B.m[3 + j]
                           + A.m[3 * i + 2] * B.m[6 + j];
        }
        r.t[i] = A.m[3 * i + 0] * B.t[0]
               + A.m[3 * i + 1] * B.t[1]
               + A.m[3 * i + 2] * B.t[2] + A.t[i];
    }
    return r;
}

__device__ __forceinline__ Aff invRigid(const Aff& A) {
    Aff r;
    r.m[0] = A.m[0]; r.m[1] = A.m[3]; r.m[2] = A.m[6];
    r.m[3] = A.m[1]; r.m[4] = A.m[4]; r.m[5] = A.m[7];
    r.m[6] = A.m[2]; r.m[7] = A.m[5]; r.m[8] = A.m[8];
#pragma unroll
    for (int i = 0; i < 3; i++) {
        r.t[i] = -(r.m[3 * i + 0] * A.t[0] + r.m[3 * i + 1] * A.t[1] + r.m[3 * i + 2] * A.t[2]);
    }
    return r;
}

// Orthonormal placement frame: columns (ex, ey, ez), origin c.
// ex = bond dir (bc), ez = plane normal (n), ey = ez x ex (nbc).
struct Frame { V3 ex, ey, ez; V3 c; };

// One atom placement in closed form. Updates the frame, returns new atom pos.
//   u (new ex)  = -cos(ang)*ex + cos(tor)*sin(ang)*ey + sin(tor)*sin(ang)*ez
//   p           = c + len*u
//   ez'         = -sin(tor)*ey + cos(tor)*ez
//   ey'         = ez' x u
__device__ __forceinline__ V3 placeF(Frame& F, float ang, float len, float tor) {
    float st, ct, sa, ca;
    __sincosf(tor, &st, &ct);
    __sincosf(ang, &sa, &ca);
    float k2 = ct * sa, k3 = st * sa;
    V3 u  = { k3 * F.ez.x + (k2 * F.ey.x - ca * F.ex.x),
              k3 * F.ez.y + (k2 * F.ey.y - ca * F.ex.y),
              k3 * F.ez.z + (k2 * F.ey.z - ca * F.ex.z) };
    V3 p  = { F.c.x + len * u.x, F.c.y + len * u.y, F.c.z + len * u.z };
    V3 ez2 = { ct * F.ez.x - st * F.ey.x,
               ct * F.ez.y - st * F.ey.y,
               ct * F.ez.z - st * F.ey.z };
    V3 ey2 = vcross(ez2, u);
    F.ex = u; F.ey = ey2; F.ez = ez2; F.c = p;
    return p;
}

__device__ __forceinline__ Frame frameOfTriplet(V3 a, V3 b, V3 c) {
    Frame F;
    F.ex = vunit(vsub(c, b));
    F.ez = vunit(vcross(vsub(b, a), F.ex));
    F.ey = vcross(F.ez, F.ex);
    F.c = c;
    return F;
}

__device__ __forceinline__ Aff frameToAff(const Frame& F) {
    Aff A;
    A.m[0] = F.ex.x; A.m[1] = F.ey.x; A.m[2] = F.ez.x;
    A.m[3] = F.ex.y; A.m[4] = F.ey.y; A.m[5] = F.ez.y;
    A.m[6] = F.ex.z; A.m[7] = F.ey.z; A.m[8] = F.ez.z;
    A.t[0] = F.c.x;  A.t[1] = F.c.y;  A.t[2] = F.c.z;
    return A;
}

__device__ __forceinline__ Aff shflUpAff(const Aff& A, int delta) {
    Aff r;
#pragma unroll
    for (int k = 0; k < 9; k++) r.m[k] = __shfl_up_sync(0xffffffffu, A.m[k], delta);
#pragma unroll
    for (int k = 0; k < 3; k++) r.t[k] = __shfl_up_sync(0xffffffffu, A.t[k], delta);
    return r;
}

__constant__ float c9[9] = {
    17.047f, 14.099f, 3.625f,
    16.967f, 12.784f, 4.338f,
    15.685f, 12.755f, 5.133f
};

__global__ __launch_bounds__(THREADS, 6)
void nerf_kernel(const float* __restrict__ phi,
                 const float* __restrict__ psi,
                 const float* __restrict__ omega,
                 const float* __restrict__ bl,
                 const float* __restrict__ ba,
                 float* __restrict__ out) {
    __shared__ float traj[ROWS][THREADS + 1];
    __shared__ float warpTot[3][12];   // inclusive totals of warps 0..2

    const int tid  = threadIdx.x;
    const int lane = tid & 31;
    const int warp = tid >> 5;
    const int chain = blockIdx.x;

    const int base = tid * SEG;

    const V3 A0 = {17.047f, 14.099f, 3.625f};
    const V3 B0 = {16.967f, 12.784f, 4.338f};
    const V3 C0 = {15.685f, 12.755f, 5.133f};

    const float* __restrict__ phiR = phi   + (size_t)chain * L_CONST;
    const float* __restrict__ psiS = psi   + (size_t)chain * L_CONST + base;
    const float* __restrict__ omgS = omega + (size_t)chain * L_CONST + base;
    const float* __restrict__ blS  = bl + (size_t)chain * L_CONST * 3 + 3 * base;
    const float* __restrict__ baS  = ba + (size_t)chain * L_CONST * 3 + 3 * base;

    // ---- Batched vector loads of this thread's 4-step inputs ----
    float4 psq = *(const float4*)psiS;
    float4 omq = *(const float4*)omgS;
    float4 blq[3], baq[3];
#pragma unroll
    for (int q = 0; q < 3; q++) {
        blq[q] = *(const float4*)(blS + 4 * q);
        baq[q] = *(const float4*)(baS + 4 * q);
    }
    float4 phq = *(const float4*)(phiR + base);   // phi[base .. base+3]
    float ph3 = __shfl_down_sync(0xffffffffu, phq.x, 1);   // phi[base+4]
    if (lane == 31) {
        int ip = base + SEG;
        ph3 = (ip < L_CONST) ? phiR[ip] : 0.f;
    }
    float phv[4] = { phq.y, phq.z, phq.w, ph3 };
    const float* psf = (const float*)&psq;
    const float* omf = (const float*)&omq;
    const float* blf = (const float*)blq;
    const float* baf = (const float*)baq;

    // ---- Pass 1: closed-form frame propagation from canonical init ----
    Frame Fr = frameOfTriplet(A0, B0, C0);
#pragma unroll
    for (int t = 0; t < SEG; t++) {
        int i = base + t;
        if (i < NSTEP) {
            V3 p1 = placeF(Fr, baf[3 * t + 1], blf[3 * t + 2], psf[t]);
            V3 p2 = placeF(Fr, baf[3 * t + 2], blf[3 * t + 0], omf[t]);
            V3 p3 = placeF(Fr, baf[3 * t + 0], blf[3 * t + 1], phv[t]);
            traj[9 * t + 0][tid] = p1.x; traj[9 * t + 1][tid] = p1.y; traj[9 * t + 2][tid] = p1.z;
            traj[9 * t + 3][tid] = p2.x; traj[9 * t + 4][tid] = p2.y; traj[9 * t + 5][tid] = p2.z;
            traj[9 * t + 6][tid] = p3.x; traj[9 * t + 7][tid] = p3.y; traj[9 * t + 8][tid] = p3.z;
        }
    }

    // ---- Conjugated segment transform: H' = F(end) o F0^-1 ----
    const Aff F0i = invRigid(frameToAff(frameOfTriplet(A0, B0, C0)));
    Aff P = compose(frameToAff(Fr), F0i);

    // Warp inclusive Kogge-Stone scan
#pragma unroll
    for (int off = 1; off < 32; off <<= 1) {
        Aff prev = shflUpAff(P, off);
        Aff comb = compose(prev, P);
        if (lane >= off) P = comb;
    }

    // Publish warp totals
    if (lane == 31 && warp < 3) {
#pragma unroll
        for (int k = 0; k < 9; k++) warpTot[warp][k] = P.m[k];
#pragma unroll
        for (int k = 0; k < 3; k++) warpTot[warp][9 + k] = P.t[k];
    }

    Aff Pex = shflUpAff(P, 1);   // warp-local exclusive prefix
    __syncthreads();

    // W = warpTot[0] o ... o warpTot[warp-1] o Pex   (exclusive prefix = W)
    Aff W = (lane == 0) ? identityAff() : Pex;
    for (int v = warp - 1; v >= 0; v--) {
        Aff T;
#pragma unroll
        for (int k = 0; k < 9; k++) T.m[k] = warpTot[v][k];
#pragma unroll
        for (int k = 0; k < 3; k++) T.t[k] = warpTot[v][9 + k];
        W = compose(T, W);
    }

    // ---- Pass 2: transform local trajectory in SMEM ----
#pragma unroll
    for (int s = 0; s < SEG; s++) {
#pragma unroll
        for (int p = 0; p < 3; p++) {
            V3 v;
            v.x = traj[9 * s + 3 * p + 0][tid];
            v.y = traj[9 * s + 3 * p + 1][tid];
            v.z = traj[9 * s + 3 * p + 2][tid];
            float wx = W.m[0] * v.x + W.m[1] * v.y + W.m[2] * v.z + W.t[0];
            float wy = W.m[3] * v.x + W.m[4] * v.y + W.m[5] * v.z + W.t[1];
            float wz = W.m[6] * v.x + W.m[7] * v.y + W.m[8] * v.z + W.t[2];
            traj[9 * s + 3 * p + 0][tid] = wx;
            traj[9 * s + 3 * p + 1][tid] = wy;
            traj[9 * s + 3 * p + 2][tid] = wz;
        }
    }
    __syncthreads();

    // ---- Coalesced cooperative writeout: 4608 contiguous floats/chain ----
    float* __restrict__ outC = out + (size_t)chain * CHAIN_FLOATS;
#pragma unroll
    for (int it = 0; it < CHAIN_FLOATS / THREADS; it++) {
        int f = it * THREADS + tid;
        float v;
        if (f < 9) {
            v = c9[f];
        } else {
            int g = f - 9;
            int i = g / 9;            // global step index
            int owner = i >> 2;       // owning thread (SEG=4)
            int row = g - ROWS * owner;
            v = traj[row][owner];
        }
        outC[f] = v;
    }
}

} // anonymous namespace

extern "C" void kernel_launch(void* const* d_in, const int* in_sizes, int n_in,
                              void* d_out, int out_size) {
    const float* phi   = (const float*)d_in[0];
    const float* psi   = (const float*)d_in[1];
    const float* omega = (const float*)d_in[2];
    const float* bl    = (const float*)d_in[3];
    const float* ba    = (const float*)d_in[4];

    const int B = in_sizes[0] / L_CONST;

    nerf_kernel<<<B, THREADS>>>(phi, psi, omega, bl, ba, (float*)d_out);
}